// round 2
// baseline (speedup 1.0000x reference)
#include <cuda_runtime.h>
#include <cstdint>
#include <cstddef>

// Problem constants
#define BB 4
#define TT 8
#define HH 64
#define WW 64
#define CC 32
#define FF 32
#define HWPX 4096          // 64*64
#define OC4F 128           // 4*F

// Scratch buffers (device globals -- no allocation allowed)
__device__ float g_xz[(size_t)BB * TT * HWPX * OC4F];   // 16.8M floats: input-conv results + bias
__device__ float g_z [(size_t)BB * HWPX * OC4F];        // per-step pre-activation z
__device__ float g_h [(size_t)BB * HWPX * FF];          // hidden state
__device__ float g_c [(size_t)BB * HWPX * FF];          // cell state
__device__ float g_l0[(size_t)BB * TT * HWPX * FF];     // layer-0 output (layer-1 input + residual)

// smem layout (floats): input tile 324*33 = 10692 | weights 288*32 = 9216 | bn 64
#define SM_IN   0
#define SM_W    10692
#define SM_BN   (10692 + 9216)
#define SM_FLOATS (10692 + 9216 + 64)

// ---------------------------------------------------------------------------
// 3x3 conv, Cin=32 -> Cout=128 (this block handles a 32-oc slice).
// Block: 256 threads, 16x16 pixel tile, 32 output channels.
// Thread: 4 consecutive x-pixels * 8 output channels = 32 accumulators.
// IS_INPUT: apply BN (scale/shift) to loaded input, add bias to acc.
// !IS_INPUT: plain input (h state), add addsrc (xz slice) in epilogue.
// ---------------------------------------------------------------------------
template<bool IS_INPUT>
__global__ __launch_bounds__(256, 2)
void conv3x3(const float* __restrict__ in,       // frames of [64,64,32], stride HWPX*CC
             const float* __restrict__ wg,       // [3,3,32,128]
             const float* __restrict__ bias,     // [128] (IS_INPUT only)
             const float* __restrict__ gma,
             const float* __restrict__ bta,
             const float* __restrict__ mu,
             const float* __restrict__ var,
             const float* __restrict__ addsrc,   // frames of [64,64,128] (!IS_INPUT only)
             size_t add_fs,
             float* __restrict__ out,            // frames of [64,64,128]
             size_t out_fs)
{
    extern __shared__ float sm[];
    float* in_s = sm + SM_IN;
    float* w_s  = sm + SM_W;
    float* bn_s = sm + SM_BN;

    const int tid   = threadIdx.x;
    const int frame = blockIdx.z;
    const int ocblk = blockIdx.y;                 // 0..3 -> oc base ocblk*32
    const int ty    = blockIdx.x >> 2;
    const int tx    = blockIdx.x & 3;

    const float* inf = in + (size_t)frame * (HWPX * CC);

    if (IS_INPUT) {
        if (tid < 32) {
            float s = gma[tid] * rsqrtf(var[tid] + 1e-3f);
            bn_s[tid]      = s;
            bn_s[32 + tid] = bta[tid] - mu[tid] * s;
        }
        __syncthreads();
    }

    // Load 18x18 halo tile, channel-padded smem layout: pix*33 + c
    for (int idx = tid; idx < 324 * 8; idx += 256) {
        int px = idx >> 3;
        int cq = (idx & 7) << 2;
        int ly = px / 18, lx = px - ly * 18;
        int gy = (ty << 4) + ly - 1;
        int gx = (tx << 4) + lx - 1;
        float4 v = make_float4(0.f, 0.f, 0.f, 0.f);
        if ((unsigned)gy < 64u && (unsigned)gx < 64u) {
            v = *reinterpret_cast<const float4*>(inf + (((gy << 6) + gx) * CC + cq));
            if (IS_INPUT) {
                v.x = fmaf(v.x, bn_s[cq + 0], bn_s[32 + cq + 0]);
                v.y = fmaf(v.y, bn_s[cq + 1], bn_s[32 + cq + 1]);
                v.z = fmaf(v.z, bn_s[cq + 2], bn_s[32 + cq + 2]);
                v.w = fmaf(v.w, bn_s[cq + 3], bn_s[32 + cq + 3]);
            }
        }
        float* d = in_s + px * 33 + cq;
        d[0] = v.x; d[1] = v.y; d[2] = v.z; d[3] = v.w;
    }

    // Load weight slice: [9 taps][32 cin][32 oc]
    for (int idx = tid; idx < 2304; idx += 256) {
        int row = idx >> 3;            // tap*32 + cin
        int q   = (idx & 7) << 2;
        *reinterpret_cast<float4*>(w_s + (row << 5) + q) =
            *reinterpret_cast<const float4*>(wg + ((size_t)row << 7) + (ocblk << 5) + q);
    }
    __syncthreads();

    const int ocg = tid & 3;
    const int pg  = tid >> 2;
    const int py  = pg >> 2;           // 0..15
    const int x0  = (pg & 3) << 2;     // 0,4,8,12
    const int oc0 = ocg << 3;          // 0,8,16,24

    float acc[4][8];
    if (IS_INPUT) {
        #pragma unroll
        for (int j = 0; j < 8; ++j) {
            float b = bias[(ocblk << 5) + oc0 + j];
            acc[0][j] = b; acc[1][j] = b; acc[2][j] = b; acc[3][j] = b;
        }
    } else {
        #pragma unroll
        for (int j = 0; j < 8; ++j) {
            acc[0][j] = 0.f; acc[1][j] = 0.f; acc[2][j] = 0.f; acc[3][j] = 0.f;
        }
    }

    #pragma unroll 2
    for (int cin = 0; cin < 32; ++cin) {
        #pragma unroll
        for (int dy = 0; dy < 3; ++dy) {
            const float* ib = in_s + ((py + dy) * 18 + x0) * 33 + cin;
            float iv[6];
            #pragma unroll
            for (int j = 0; j < 6; ++j) iv[j] = ib[j * 33];
            #pragma unroll
            for (int dx = 0; dx < 3; ++dx) {
                const float4* wv = reinterpret_cast<const float4*>(
                    w_s + (((dy * 3 + dx) << 5) + cin) * 32 + oc0);
                float4 w0 = wv[0];
                float4 w1 = wv[1];
                #pragma unroll
                for (int p = 0; p < 4; ++p) {
                    float v = iv[p + dx];
                    acc[p][0] = fmaf(v, w0.x, acc[p][0]);
                    acc[p][1] = fmaf(v, w0.y, acc[p][1]);
                    acc[p][2] = fmaf(v, w0.z, acc[p][2]);
                    acc[p][3] = fmaf(v, w0.w, acc[p][3]);
                    acc[p][4] = fmaf(v, w1.x, acc[p][4]);
                    acc[p][5] = fmaf(v, w1.y, acc[p][5]);
                    acc[p][6] = fmaf(v, w1.z, acc[p][6]);
                    acc[p][7] = fmaf(v, w1.w, acc[p][7]);
                }
            }
        }
    }

    const int gy = (ty << 4) + py;
    #pragma unroll
    for (int p = 0; p < 4; ++p) {
        int gx = (tx << 4) + x0 + p;
        size_t pixoff = (size_t)(((gy << 6) + gx) << 7) + (ocblk << 5) + oc0;
        float4 a0 = make_float4(acc[p][0], acc[p][1], acc[p][2], acc[p][3]);
        float4 a1 = make_float4(acc[p][4], acc[p][5], acc[p][6], acc[p][7]);
        if (!IS_INPUT) {
            size_t ai = (size_t)frame * add_fs + pixoff;
            float4 b0 = *reinterpret_cast<const float4*>(addsrc + ai);
            float4 b1 = *reinterpret_cast<const float4*>(addsrc + ai + 4);
            a0.x += b0.x; a0.y += b0.y; a0.z += b0.z; a0.w += b0.w;
            a1.x += b1.x; a1.y += b1.y; a1.z += b1.z; a1.w += b1.w;
        }
        size_t o = (size_t)frame * out_fs + pixoff;
        *reinterpret_cast<float4*>(out + o)     = a0;
        *reinterpret_cast<float4*>(out + o + 4) = a1;
    }
}

// ---------------------------------------------------------------------------
// Elementwise LSTM gate update. One thread = 4 F-channels of one pixel.
// total threads = B*HW*8 = 131072 (exact grid).
// ---------------------------------------------------------------------------
__device__ __forceinline__ float hsig(float x) {
    return __saturatef(fmaf(x, 0.2f, 0.5f));
}

__global__ __launch_bounds__(256)
void gate_kernel(const float* __restrict__ z, size_t z_fs,
                 int first, int t,
                 float* __restrict__ outb,
                 const float* __restrict__ res)
{
    int idx = blockIdx.x * 256 + threadIdx.x;
    int p   = idx >> 3;            // pixel in [0, B*HW)
    int g   = (idx & 7) << 2;      // f-channel base
    int b   = p >> 12;
    int pix = p & 4095;

    const float* zp = z + (size_t)b * z_fs + (size_t)pix * OC4F + g;
    float4 zi = *reinterpret_cast<const float4*>(zp);
    float4 zf = *reinterpret_cast<const float4*>(zp + 32);
    float4 zc = *reinterpret_cast<const float4*>(zp + 64);
    float4 zo = *reinterpret_cast<const float4*>(zp + 96);

    size_t ci = (size_t)p * FF + g;
    float4 cp = first ? make_float4(0.f, 0.f, 0.f, 0.f)
                      : *reinterpret_cast<const float4*>(g_c + ci);

    float4 cn, hv;
    cn.x = hsig(zf.x) * cp.x + hsig(zi.x) * tanhf(zc.x);
    cn.y = hsig(zf.y) * cp.y + hsig(zi.y) * tanhf(zc.y);
    cn.z = hsig(zf.z) * cp.z + hsig(zi.z) * tanhf(zc.z);
    cn.w = hsig(zf.w) * cp.w + hsig(zi.w) * tanhf(zc.w);
    hv.x = hsig(zo.x) * tanhf(cn.x);
    hv.y = hsig(zo.y) * tanhf(cn.y);
    hv.z = hsig(zo.z) * tanhf(cn.z);
    hv.w = hsig(zo.w) * tanhf(cn.w);

    *reinterpret_cast<float4*>(g_c + ci) = cn;
    *reinterpret_cast<float4*>(g_h + ci) = hv;   // raw h carried into recurrence

    size_t oo = ((size_t)(b * TT + t) * HWPX + pix) * FF + g;
    if (res != nullptr) {
        float4 r = *reinterpret_cast<const float4*>(res + oo);
        hv.x += r.x; hv.y += r.y; hv.z += r.z; hv.w += r.w;
    }
    *reinterpret_cast<float4*>(outb + oo) = hv;
}

// ---------------------------------------------------------------------------
extern "C" void kernel_launch(void* const* d_in, const int* in_sizes, int n_in,
                              void* d_out, int out_size)
{
    (void)in_sizes; (void)n_in; (void)out_size;
    const float* x    = (const float*)d_in[0];
    const float* gma  = (const float*)d_in[1];
    const float* bta  = (const float*)d_in[2];
    const float* mu   = (const float*)d_in[3];
    const float* var  = (const float*)d_in[4];
    const float* ker  = (const float*)d_in[5];   // [2,3,3,32,128]
    const float* rker = (const float*)d_in[6];   // [2,3,3,32,128]
    const float* bias = (const float*)d_in[7];   // [2,128]

    float *xz, *zz, *l0, *hptr;
    cudaGetSymbolAddress((void**)&xz,   g_xz);
    cudaGetSymbolAddress((void**)&zz,   g_z);
    cudaGetSymbolAddress((void**)&l0,   g_l0);
    cudaGetSymbolAddress((void**)&hptr, g_h);

    const size_t SMEM = (size_t)SM_FLOATS * sizeof(float);
    cudaFuncSetAttribute((const void*)conv3x3<true>,
                         cudaFuncAttributeMaxDynamicSharedMemorySize, (int)SMEM);
    cudaFuncSetAttribute((const void*)conv3x3<false>,
                         cudaFuncAttributeMaxDynamicSharedMemorySize, (int)SMEM);

    const size_t XZ_FS  = (size_t)HWPX * OC4F;        // frame stride inside g_xz (per (b,t))
    const size_t XZ_BFS = (size_t)TT * HWPX * OC4F;   // per-b stride

    for (int l = 0; l < 2; ++l) {
        const float* lin  = (l == 0) ? x : l0;
        float*       outb = (l == 0) ? l0 : (float*)d_out;
        const float* res  = (l == 0) ? nullptr : l0;

        // Input-to-hidden conv + folded BN + bias, all B*T frames at once
        conv3x3<true><<<dim3(16, 4, BB * TT), 256, SMEM>>>(
            lin, ker + (size_t)l * 36864, bias + l * OC4F,
            gma + l * CC, bta + l * CC, mu + l * CC, var + l * CC,
            nullptr, 0, xz, XZ_FS);

        // t = 0: h0 = 0 -> z = xz[:,0], c0 = 0
        gate_kernel<<<512, 256>>>(xz, XZ_BFS, 1, 0, outb, res);

        for (int t = 1; t < TT; ++t) {
            conv3x3<false><<<dim3(16, 4, BB), 256, SMEM>>>(
                hptr, rker + (size_t)l * 36864, nullptr,
                nullptr, nullptr, nullptr, nullptr,
                xz + (size_t)t * XZ_FS, XZ_BFS,
                zz, XZ_FS);
            gate_kernel<<<512, 256>>>(zz, XZ_FS, 0, t, outb, res);
        }
    }
}

// round 3
// speedup vs baseline: 1.0754x; 1.0754x over previous
#include <cuda_runtime.h>
#include <cstdint>
#include <cstddef>

// Problem constants
#define BB 4
#define TT 8
#define HH 64
#define WW 64
#define CC 32
#define FF 32
#define HWPX 4096          // 64*64
#define OC4F 128           // 4*F

// Scratch buffers (device globals -- no allocation allowed)
__device__ float g_xz[(size_t)BB * TT * HWPX * OC4F];   // input-conv results + bias
__device__ float g_z [(size_t)BB * HWPX * OC4F];        // per-step pre-activation z
__device__ float g_h [(size_t)BB * HWPX * FF];          // hidden state
__device__ float g_c [(size_t)BB * HWPX * FF];          // cell state
__device__ float g_l0[(size_t)BB * TT * HWPX * FF];     // layer-0 output (layer-1 input + residual)

// smem layout (floats): input tile 324*33 = 10692 | weights 288*32 = 9216 | bn 64
#define SM_IN   0
#define SM_W    10692
#define SM_BN   (10692 + 9216)
#define SM_FLOATS (10692 + 9216 + 64)

// ---------------- packed f32x2 helpers (sm_103a FFMA2 path) ----------------
typedef unsigned long long u64;

__device__ __forceinline__ u64 pack2(float v) {
    u64 r;
    asm("mov.b64 %0, {%1, %1};" : "=l"(r) : "f"(v));
    return r;
}
__device__ __forceinline__ u64 pack2f(float a, float b) {
    u64 r;
    asm("mov.b64 %0, {%1, %2};" : "=l"(r) : "f"(a), "f"(b));
    return r;
}
__device__ __forceinline__ void fma2(u64& d, u64 a, u64 b) {
    asm("fma.rn.f32x2 %0, %1, %2, %0;" : "+l"(d) : "l"(a), "l"(b));
}
__device__ __forceinline__ u64 add2(u64 a, u64 b) {
    u64 r;
    asm("add.rn.f32x2 %0, %1, %2;" : "=l"(r) : "l"(a), "l"(b));
    return r;
}

// ---------------------------------------------------------------------------
// 3x3 conv, Cin=32 -> Cout=128 (this block handles a 32-oc slice).
// Block: 256 threads, 16x16 pixel tile, 32 output channels.
// Thread: 4 consecutive x-pixels * 8 output channels (as 4 packed f32x2 accs).
// IS_INPUT: apply BN (scale/shift) to loaded input, add bias to acc.
// !IS_INPUT: plain input (h state), add addsrc (xz slice) in epilogue.
// ---------------------------------------------------------------------------
template<bool IS_INPUT>
__global__ __launch_bounds__(256, 2)
void conv3x3(const float* __restrict__ in,       // frames of [64,64,32]
             const float* __restrict__ wg,       // [3,3,32,128]
             const float* __restrict__ bias,     // [128] (IS_INPUT only)
             const float* __restrict__ gma,
             const float* __restrict__ bta,
             const float* __restrict__ mu,
             const float* __restrict__ var,
             const float* __restrict__ addsrc,   // frames of [64,64,128] (!IS_INPUT only)
             size_t add_fs,
             float* __restrict__ out,            // frames of [64,64,128]
             size_t out_fs)
{
    extern __shared__ float sm[];
    float* in_s = sm + SM_IN;
    float* w_s  = sm + SM_W;
    float* bn_s = sm + SM_BN;

    const int tid   = threadIdx.x;
    const int frame = blockIdx.z;
    const int ocblk = blockIdx.y;                 // 0..3 -> oc base ocblk*32
    const int ty    = blockIdx.x >> 2;
    const int tx    = blockIdx.x & 3;

    const float* inf = in + (size_t)frame * (HWPX * CC);

    if (IS_INPUT) {
        if (tid < 32) {
            float s = gma[tid] * rsqrtf(var[tid] + 1e-3f);
            bn_s[tid]      = s;
            bn_s[32 + tid] = bta[tid] - mu[tid] * s;
        }
        __syncthreads();
    }

    // Load 18x18 halo tile, channel-padded smem layout: pix*33 + c
    for (int idx = tid; idx < 324 * 8; idx += 256) {
        int px = idx >> 3;
        int cq = (idx & 7) << 2;
        int ly = px / 18, lx = px - ly * 18;
        int gy = (ty << 4) + ly - 1;
        int gx = (tx << 4) + lx - 1;
        float4 v = make_float4(0.f, 0.f, 0.f, 0.f);
        if ((unsigned)gy < 64u && (unsigned)gx < 64u) {
            v = *reinterpret_cast<const float4*>(inf + (((gy << 6) + gx) * CC + cq));
            if (IS_INPUT) {
                v.x = fmaf(v.x, bn_s[cq + 0], bn_s[32 + cq + 0]);
                v.y = fmaf(v.y, bn_s[cq + 1], bn_s[32 + cq + 1]);
                v.z = fmaf(v.z, bn_s[cq + 2], bn_s[32 + cq + 2]);
                v.w = fmaf(v.w, bn_s[cq + 3], bn_s[32 + cq + 3]);
            }
        }
        float* d = in_s + px * 33 + cq;
        d[0] = v.x; d[1] = v.y; d[2] = v.z; d[3] = v.w;
    }

    // Load weight slice: [9 taps][32 cin][32 oc]
    for (int idx = tid; idx < 2304; idx += 256) {
        int row = idx >> 3;            // tap*32 + cin
        int q   = (idx & 7) << 2;
        *reinterpret_cast<float4*>(w_s + (row << 5) + q) =
            *reinterpret_cast<const float4*>(wg + ((size_t)row << 7) + (ocblk << 5) + q);
    }
    __syncthreads();

    const int ocg = tid & 3;
    const int pg  = tid >> 2;
    const int py  = pg >> 2;           // 0..15
    const int x0  = (pg & 3) << 2;     // 0,4,8,12
    const int oc0 = ocg << 3;          // 0,8,16,24

    // acc[p][j] = packed pair (oc0+2j, oc0+2j+1) for pixel x0+p
    u64 acc[4][4];
    if (IS_INPUT) {
        #pragma unroll
        for (int j = 0; j < 4; ++j) {
            u64 b = pack2f(bias[(ocblk << 5) + oc0 + 2 * j],
                           bias[(ocblk << 5) + oc0 + 2 * j + 1]);
            acc[0][j] = b; acc[1][j] = b; acc[2][j] = b; acc[3][j] = b;
        }
    } else {
        #pragma unroll
        for (int j = 0; j < 4; ++j) {
            acc[0][j] = 0ull; acc[1][j] = 0ull; acc[2][j] = 0ull; acc[3][j] = 0ull;
        }
    }

    for (int cin = 0; cin < 32; ++cin) {
        #pragma unroll
        for (int dy = 0; dy < 3; ++dy) {
            const float* ib = in_s + ((py + dy) * 18 + x0) * 33 + cin;
            u64 pv[6];
            #pragma unroll
            for (int j = 0; j < 6; ++j) pv[j] = pack2(ib[j * 33]);
            #pragma unroll
            for (int dx = 0; dx < 3; ++dx) {
                const ulonglong2* wv = reinterpret_cast<const ulonglong2*>(
                    w_s + (((dy * 3 + dx) << 5) + cin) * 32 + oc0);
                ulonglong2 wa = wv[0];   // (oc0,oc1) (oc2,oc3)
                ulonglong2 wb = wv[1];   // (oc4,oc5) (oc6,oc7)
                #pragma unroll
                for (int p = 0; p < 4; ++p) {
                    u64 v = pv[p + dx];
                    fma2(acc[p][0], v, wa.x);
                    fma2(acc[p][1], v, wa.y);
                    fma2(acc[p][2], v, wb.x);
                    fma2(acc[p][3], v, wb.y);
                }
            }
        }
    }

    const int gy = (ty << 4) + py;
    #pragma unroll
    for (int p = 0; p < 4; ++p) {
        int gx = (tx << 4) + x0 + p;
        size_t pixoff = (size_t)(((gy << 6) + gx) << 7) + (ocblk << 5) + oc0;
        u64 r0 = acc[p][0], r1 = acc[p][1], r2 = acc[p][2], r3 = acc[p][3];
        if (!IS_INPUT) {
            size_t ai = (size_t)frame * add_fs + pixoff;
            ulonglong2 b0 = *reinterpret_cast<const ulonglong2*>(addsrc + ai);
            ulonglong2 b1 = *reinterpret_cast<const ulonglong2*>(addsrc + ai + 4);
            r0 = add2(r0, b0.x); r1 = add2(r1, b0.y);
            r2 = add2(r2, b1.x); r3 = add2(r3, b1.y);
        }
        size_t o = (size_t)frame * out_fs + pixoff;
        ulonglong2 s0; s0.x = r0; s0.y = r1;
        ulonglong2 s1; s1.x = r2; s1.y = r3;
        *reinterpret_cast<ulonglong2*>(out + o)     = s0;
        *reinterpret_cast<ulonglong2*>(out + o + 4) = s1;
    }
}

// ---------------------------------------------------------------------------
// Elementwise LSTM gate update. One thread = 4 F-channels of one pixel.
// total threads = B*HW*8 = 131072 (exact grid).
// ---------------------------------------------------------------------------
__device__ __forceinline__ float hsig(float x) {
    return __saturatef(fmaf(x, 0.2f, 0.5f));
}

__global__ __launch_bounds__(256)
void gate_kernel(const float* __restrict__ z, size_t z_fs,
                 int first, int t,
                 float* __restrict__ outb,
                 const float* __restrict__ res)
{
    int idx = blockIdx.x * 256 + threadIdx.x;
    int p   = idx >> 3;            // pixel in [0, B*HW)
    int g   = (idx & 7) << 2;      // f-channel base
    int b   = p >> 12;
    int pix = p & 4095;

    const float* zp = z + (size_t)b * z_fs + (size_t)pix * OC4F + g;
    float4 zi = *reinterpret_cast<const float4*>(zp);
    float4 zf = *reinterpret_cast<const float4*>(zp + 32);
    float4 zc = *reinterpret_cast<const float4*>(zp + 64);
    float4 zo = *reinterpret_cast<const float4*>(zp + 96);

    size_t ci = (size_t)p * FF + g;
    float4 cp = first ? make_float4(0.f, 0.f, 0.f, 0.f)
                      : *reinterpret_cast<const float4*>(g_c + ci);

    float4 cn, hv;
    cn.x = hsig(zf.x) * cp.x + hsig(zi.x) * tanhf(zc.x);
    cn.y = hsig(zf.y) * cp.y + hsig(zi.y) * tanhf(zc.y);
    cn.z = hsig(zf.z) * cp.z + hsig(zi.z) * tanhf(zc.z);
    cn.w = hsig(zf.w) * cp.w + hsig(zi.w) * tanhf(zc.w);
    hv.x = hsig(zo.x) * tanhf(cn.x);
    hv.y = hsig(zo.y) * tanhf(cn.y);
    hv.z = hsig(zo.z) * tanhf(cn.z);
    hv.w = hsig(zo.w) * tanhf(cn.w);

    *reinterpret_cast<float4*>(g_c + ci) = cn;
    *reinterpret_cast<float4*>(g_h + ci) = hv;   // raw h carried into recurrence

    size_t oo = ((size_t)(b * TT + t) * HWPX + pix) * FF + g;
    if (res != nullptr) {
        float4 r = *reinterpret_cast<const float4*>(res + oo);
        hv.x += r.x; hv.y += r.y; hv.z += r.z; hv.w += r.w;
    }
    *reinterpret_cast<float4*>(outb + oo) = hv;
}

// ---------------------------------------------------------------------------
extern "C" void kernel_launch(void* const* d_in, const int* in_sizes, int n_in,
                              void* d_out, int out_size)
{
    (void)in_sizes; (void)n_in; (void)out_size;
    const float* x    = (const float*)d_in[0];
    const float* gma  = (const float*)d_in[1];
    const float* bta  = (const float*)d_in[2];
    const float* mu   = (const float*)d_in[3];
    const float* var  = (const float*)d_in[4];
    const float* ker  = (const float*)d_in[5];   // [2,3,3,32,128]
    const float* rker = (const float*)d_in[6];   // [2,3,3,32,128]
    const float* bias = (const float*)d_in[7];   // [2,128]

    float *xz, *zz, *l0, *hptr;
    cudaGetSymbolAddress((void**)&xz,   g_xz);
    cudaGetSymbolAddress((void**)&zz,   g_z);
    cudaGetSymbolAddress((void**)&l0,   g_l0);
    cudaGetSymbolAddress((void**)&hptr, g_h);

    const size_t SMEM = (size_t)SM_FLOATS * sizeof(float);
    cudaFuncSetAttribute((const void*)conv3x3<true>,
                         cudaFuncAttributeMaxDynamicSharedMemorySize, (int)SMEM);
    cudaFuncSetAttribute((const void*)conv3x3<false>,
                         cudaFuncAttributeMaxDynamicSharedMemorySize, (int)SMEM);

    const size_t XZ_FS  = (size_t)HWPX * OC4F;        // frame stride inside g_xz (per (b,t))
    const size_t XZ_BFS = (size_t)TT * HWPX * OC4F;   // per-b stride

    for (int l = 0; l < 2; ++l) {
        const float* lin  = (l == 0) ? x : l0;
        float*       outb = (l == 0) ? l0 : (float*)d_out;
        const float* res  = (l == 0) ? nullptr : l0;

        // Input-to-hidden conv + folded BN + bias, all B*T frames at once
        conv3x3<true><<<dim3(16, 4, BB * TT), 256, SMEM>>>(
            lin, ker + (size_t)l * 36864, bias + l * OC4F,
            gma + l * CC, bta + l * CC, mu + l * CC, var + l * CC,
            nullptr, 0, xz, XZ_FS);

        // t = 0: h0 = 0 -> z = xz[:,0], c0 = 0
        gate_kernel<<<512, 256>>>(xz, XZ_BFS, 1, 0, outb, res);

        for (int t = 1; t < TT; ++t) {
            conv3x3<false><<<dim3(16, 4, BB), 256, SMEM>>>(
                hptr, rker + (size_t)l * 36864, nullptr,
                nullptr, nullptr, nullptr, nullptr,
                xz + (size_t)t * XZ_FS, XZ_BFS,
                zz, XZ_FS);
            gate_kernel<<<512, 256>>>(zz, XZ_FS, 0, t, outb, res);
        }
    }
}

// round 4
// speedup vs baseline: 2.1446x; 1.9943x over previous
#include <cuda_runtime.h>
#include <cuda_fp16.h>
#include <cstdint>
#include <cstddef>

#define NB 4
#define NT 8
#define HWPX 4096
#define NFRM 32          // NB*NT

// ---------------- device scratch ----------------
__device__ __half g_xf16 [(size_t)NFRM * HWPX * 32];   // layer-0 conv input (BN folded, fp16, swizzled)
__device__ __half g_x2f16[(size_t)NFRM * HWPX * 32];   // layer-1 conv input (BN folded, fp16, swizzled)
__device__ __half g_w16  [2 * 9 * 128 * 32];           // input kernels  [l][tap][oc][cin'] fp16 swizzled
__device__ __half g_rw16 [2 * 9 * 128 * 32];           // recur. kernels
__device__ float  g_xz   [(size_t)NFRM * HWPX * 128];  // xz = conv(in)+bias, fp32
__device__ float  g_c    [(size_t)NB * HWPX * 32];     // cell state fp32
__device__ __half g_h16  [(size_t)NB * HWPX * 32];     // hidden state fp16 swizzled
__device__ float  g_l0   [(size_t)NFRM * HWPX * 32];   // layer-0 output fp32 (residual source)

__device__ __forceinline__ float hsig(float x) { return __saturatef(fmaf(x, 0.2f, 0.5f)); }

__device__ __forceinline__ void ldsm4(unsigned* r, unsigned saddr) {
    asm volatile("ldmatrix.sync.aligned.m8n8.x4.shared.b16 {%0,%1,%2,%3}, [%4];\n"
        : "=r"(r[0]), "=r"(r[1]), "=r"(r[2]), "=r"(r[3]) : "r"(saddr));
}
__device__ __forceinline__ void mma16816(float* d, const unsigned* a, const unsigned* b) {
    asm volatile("mma.sync.aligned.m16n8k16.row.col.f32.f16.f16.f32 "
        "{%0,%1,%2,%3}, {%4,%5,%6,%7}, {%8,%9}, {%0,%1,%2,%3};\n"
        : "+f"(d[0]), "+f"(d[1]), "+f"(d[2]), "+f"(d[3])
        : "r"(a[0]), "r"(a[1]), "r"(a[2]), "r"(a[3]), "r"(b[0]), "r"(b[1]));
}

// ---------------- prep: weights fp32 [l][3][3][cin][oc] -> fp16 [l][tap][oc][cin swizzled]
__global__ void prep_w(const float* __restrict__ ker, const float* __restrict__ rker) {
    int idx = blockIdx.x * 256 + threadIdx.x;
    if (idx >= 2 * 73728) return;
    int tsel = idx >= 73728;
    int rem  = idx - tsel * 73728;
    const float* src = tsel ? rker : ker;
    __half* dst = tsel ? g_rw16 : g_w16;
    int l   = rem / 36864;
    int r2  = rem - l * 36864;
    int tap = r2 >> 12;
    int r3  = r2 & 4095;
    int cin = r3 >> 7;
    int oc  = r3 & 127;
    int sch = (cin >> 3) ^ ((oc >> 1) & 3);
    dst[l * 36864 + tap * 4096 + oc * 32 + sch * 8 + (cin & 7)] = __float2half(src[rem]);
}

// ---------------- prep: layer-0 input, BN fold + fp16 + swizzle
__global__ void prep_x(const float* __restrict__ x, const float* __restrict__ gma,
                       const float* __restrict__ bta, const float* __restrict__ mu,
                       const float* __restrict__ var) {
    int idx = blockIdx.x * 256 + threadIdx.x;     // 32*4096*8 threads
    int p   = idx >> 3;
    int c4  = (idx & 7) << 2;
    int xcol = p & 63;
    float4 v = *reinterpret_cast<const float4*>(x + (size_t)p * 32 + c4);
    float sc[4], bb[4];
    #pragma unroll
    for (int i = 0; i < 4; ++i) {
        float g = __ldg(gma + c4 + i);
        sc[i] = g * rsqrtf(__ldg(var + c4 + i) + 1e-3f);
        bb[i] = __ldg(bta + c4 + i) - __ldg(mu + c4 + i) * sc[i];
    }
    __half2 h0 = __floats2half2_rn(fmaf(v.x, sc[0], bb[0]), fmaf(v.y, sc[1], bb[1]));
    __half2 h1 = __floats2half2_rn(fmaf(v.z, sc[2], bb[2]), fmaf(v.w, sc[3], bb[3]));
    int sch = (c4 >> 3) ^ (((xcol + 1) >> 1) & 3);
    __half* d = g_xf16 + (size_t)p * 32 + sch * 8 + (c4 & 7);
    *reinterpret_cast<__half2*>(d)     = h0;
    *reinterpret_cast<__half2*>(d + 2) = h1;
}

// ---------------- conv (+ fused gates for MODE 1/2) ----------------
// MODE 0: xz = conv(in)+bias -> g_xz (grid.y = 32 frames)
// MODE 1: layer0 step: z = conv(h)+xz; gates; out0=h; bn->out16   (grid.y = 4 b)
// MODE 2: layer1 step: z = conv(h)+xz; gates; outF = h + res      (grid.y = 4 b)
template<int MODE>
__global__ __launch_bounds__(256, 2)
void conv_mma(const __half* __restrict__ inp, const __half* __restrict__ wsrc,
              const float* __restrict__ bias,
              const float* __restrict__ xz, float* __restrict__ cstate,
              __half* __restrict__ hstate,
              float* __restrict__ out0, __half* __restrict__ out16,
              const float* __restrict__ res, float* __restrict__ outF,
              const float* __restrict__ g1, const float* __restrict__ be1,
              const float* __restrict__ mu1, const float* __restrict__ va1,
              int t)
{
    extern __shared__ __half sm[];
    __half* in_s = sm;           // 4*66*32 = 8448 halves
    __half* B_s  = sm + 8448;    // 9*128*32 = 36864 halves

    const int tid  = threadIdx.x;
    const int lane = tid & 31, w = tid >> 5;
    const int mwarp = w >> 1, nw = w & 1;
    const int gid = lane >> 2, tig = lane & 3;
    const int y0 = blockIdx.x * 2;
    const int fz = blockIdx.y;                       // frame (MODE0) or b
    const int frame = (MODE == 0) ? fz : fz * NT + t;

    const __half* inF = inp + (size_t)fz * (HWPX * 32);

    // stage input tile (4 rows x 66 x-padded x 32c), zeros at pads
    for (int idx = tid; idx < 1056; idx += 256) {
        int r4 = idx / 264;
        int rem = idx - r4 * 264;
        int xp = rem >> 2;
        int ch = rem & 3;
        int yy = y0 - 1 + r4;
        uint4 val = make_uint4(0u, 0u, 0u, 0u);
        if (xp >= 1 && xp <= 64 && yy >= 0 && yy < 64)
            val = *reinterpret_cast<const uint4*>(inF + ((size_t)(yy * 64 + xp - 1) << 5) + ch * 8);
        *reinterpret_cast<uint4*>(in_s + (size_t)(r4 * 66 + xp) * 32 + ch * 8) = val;
    }
    // stage weights (already laid out + swizzled)
    for (int idx = tid; idx < 4608; idx += 256)
        *reinterpret_cast<uint4*>(B_s + idx * 8) =
            *reinterpret_cast<const uint4*>(wsrc + idx * 8);
    __syncthreads();

    float acc[2][8][4];
    #pragma unroll
    for (int mt = 0; mt < 2; ++mt)
        #pragma unroll
        for (int j = 0; j < 8; ++j)
            #pragma unroll
            for (int q = 0; q < 4; ++q) acc[mt][j][q] = 0.f;

    const int ylw = mwarp >> 1;
    const int xbw = (mwarp & 1) * 32;
    const int moff  = lane & 15;
    const int kselA = lane >> 4;
    const int noffB = (lane & 7) | ((lane >> 1) & 8);
    const int kselB = (lane >> 3) & 1;

    unsigned in_base = (unsigned)__cvta_generic_to_shared(in_s);
    unsigned b_base  = (unsigned)__cvta_generic_to_shared(B_s);

    #pragma unroll
    for (int tap = 0; tap < 9; ++tap) {
        const int dy = tap / 3, dx = tap % 3;
        const int yl = ylw + dy;
        #pragma unroll
        for (int h = 0; h < 2; ++h) {
            unsigned a[2][4];
            #pragma unroll
            for (int mt = 0; mt < 2; ++mt) {
                int xq = xbw + mt * 16 + moff + dx;
                int ch = (h << 1) | kselA;
                int sch = ch ^ ((xq >> 1) & 3);
                unsigned addr = in_base + (unsigned)((((yl * 66 + xq) << 5) + (sch << 3)) << 1);
                ldsm4(a[mt], addr);
            }
            unsigned bfrag[8][2];
            #pragma unroll
            for (int p = 0; p < 4; ++p) {
                int n = p * 32 + nw * 16 + noffB;
                int kc = (h << 1) | kselB;
                int sch = kc ^ ((n >> 1) & 3);
                unsigned addr = b_base + (unsigned)(((((tap * 128 + n) << 5)) + (sch << 3)) << 1);
                unsigned r[4];
                ldsm4(r, addr);
                bfrag[2 * p][0] = r[0]; bfrag[2 * p][1] = r[1];
                bfrag[2 * p + 1][0] = r[2]; bfrag[2 * p + 1][1] = r[3];
            }
            #pragma unroll
            for (int mt = 0; mt < 2; ++mt)
                #pragma unroll
                for (int j = 0; j < 8; ++j)
                    mma16816(acc[mt][j], a[mt], bfrag[j]);
        }
    }

    // BN constants for layer-2 input (MODE 1) -- 4 channels per thread
    float sbn[2][2], bbn[2][2];
    if (MODE == 1) {
        #pragma unroll
        for (int sub = 0; sub < 2; ++sub) {
            int f = nw * 16 + sub * 8 + tig * 2;
            #pragma unroll
            for (int c2 = 0; c2 < 2; ++c2) {
                float g = __ldg(g1 + f + c2);
                float s = g * rsqrtf(__ldg(va1 + f + c2) + 1e-3f);
                sbn[sub][c2] = s;
                bbn[sub][c2] = __ldg(be1 + f + c2) - __ldg(mu1 + f + c2) * s;
            }
        }
    }

    #pragma unroll
    for (int mt = 0; mt < 2; ++mt) {
        #pragma unroll
        for (int r = 0; r < 2; ++r) {
            int m = mwarp * 32 + mt * 16 + r * 8 + gid;
            int xcol = m & 63;
            int pix = (y0 + (m >> 6)) * 64 + xcol;
            if (MODE == 0) {
                float* o = outF + ((size_t)frame * HWPX + pix) * 128;
                #pragma unroll
                for (int j = 0; j < 8; ++j) {
                    int oc = (j >> 1) * 32 + nw * 16 + (j & 1) * 8 + tig * 2;
                    float2 bv = *reinterpret_cast<const float2*>(bias + oc);
                    float2 st;
                    st.x = acc[mt][j][2 * r]     + bv.x;
                    st.y = acc[mt][j][2 * r + 1] + bv.y;
                    *reinterpret_cast<float2*>(o + oc) = st;
                }
            } else {
                const float* zp = xz + ((size_t)frame * HWPX + pix) * 128;
                float zi[2][2], zf[2][2], zc[2][2], zo[2][2];
                #pragma unroll
                for (int j = 0; j < 8; ++j) {
                    int g = j >> 1, sub = j & 1;
                    int oc = g * 32 + nw * 16 + sub * 8 + tig * 2;
                    float2 zv = *reinterpret_cast<const float2*>(zp + oc);
                    float v0 = acc[mt][j][2 * r]     + zv.x;
                    float v1 = acc[mt][j][2 * r + 1] + zv.y;
                    if (g == 0)      { zi[sub][0] = v0; zi[sub][1] = v1; }
                    else if (g == 1) { zf[sub][0] = v0; zf[sub][1] = v1; }
                    else if (g == 2) { zc[sub][0] = v0; zc[sub][1] = v1; }
                    else             { zo[sub][0] = v0; zo[sub][1] = v1; }
                }
                #pragma unroll
                for (int sub = 0; sub < 2; ++sub) {
                    int f = nw * 16 + sub * 8 + tig * 2;
                    size_t ci = ((size_t)fz * HWPX + pix) * 32 + f;
                    float2 cp = *reinterpret_cast<const float2*>(cstate + ci);
                    float2 cn, hv;
                    cn.x = hsig(zf[sub][0]) * cp.x + hsig(zi[sub][0]) * tanhf(zc[sub][0]);
                    cn.y = hsig(zf[sub][1]) * cp.y + hsig(zi[sub][1]) * tanhf(zc[sub][1]);
                    hv.x = hsig(zo[sub][0]) * tanhf(cn.x);
                    hv.y = hsig(zo[sub][1]) * tanhf(cn.y);
                    *reinterpret_cast<float2*>(cstate + ci) = cn;
                    int sch = (f >> 3) ^ (((xcol + 1) >> 1) & 3);
                    *reinterpret_cast<__half2*>(hstate + ((size_t)fz * HWPX + pix) * 32
                                                + sch * 8 + (f & 7)) =
                        __floats2half2_rn(hv.x, hv.y);
                    size_t oo = ((size_t)frame * HWPX + pix) * 32 + f;
                    if (MODE == 1) {
                        *reinterpret_cast<float2*>(out0 + oo) = hv;
                        *reinterpret_cast<__half2*>(out16 + ((size_t)frame * HWPX + pix) * 32
                                                    + sch * 8 + (f & 7)) =
                            __floats2half2_rn(fmaf(hv.x, sbn[sub][0], bbn[sub][0]),
                                              fmaf(hv.y, sbn[sub][1], bbn[sub][1]));
                    } else {
                        float2 rv = *reinterpret_cast<const float2*>(res + oo);
                        float2 ov; ov.x = hv.x + rv.x; ov.y = hv.y + rv.y;
                        *reinterpret_cast<float2*>(outF + oo) = ov;
                    }
                }
            }
        }
    }
}

// ---------------- t=0 gate (h0=c0=0): z = xz ----------------
template<int MODE>   // 1: layer0, 2: layer1
__global__ __launch_bounds__(256)
void gate0(const float* __restrict__ xz, float* __restrict__ cstate,
           __half* __restrict__ hstate,
           float* __restrict__ out0, __half* __restrict__ out16,
           const float* __restrict__ res, float* __restrict__ outF,
           const float* __restrict__ g1, const float* __restrict__ be1,
           const float* __restrict__ mu1, const float* __restrict__ va1)
{
    int idx = blockIdx.x * 256 + threadIdx.x;
    int p  = idx >> 3;
    int fq = (idx & 7) << 2;
    int b = p >> 12;
    int pix = p & 4095;
    int xcol = pix & 63;
    size_t frame = (size_t)b * NT;
    const float* zp = xz + (frame * HWPX + pix) * 128 + fq;
    float4 zi = *reinterpret_cast<const float4*>(zp);
    float4 zc = *reinterpret_cast<const float4*>(zp + 64);
    float4 zo = *reinterpret_cast<const float4*>(zp + 96);
    float4 cn, hv;
    cn.x = hsig(zi.x) * tanhf(zc.x);
    cn.y = hsig(zi.y) * tanhf(zc.y);
    cn.z = hsig(zi.z) * tanhf(zc.z);
    cn.w = hsig(zi.w) * tanhf(zc.w);
    hv.x = hsig(zo.x) * tanhf(cn.x);
    hv.y = hsig(zo.y) * tanhf(cn.y);
    hv.z = hsig(zo.z) * tanhf(cn.z);
    hv.w = hsig(zo.w) * tanhf(cn.w);
    *reinterpret_cast<float4*>(cstate + (size_t)p * 32 + fq) = cn;
    int sch = (fq >> 3) ^ (((xcol + 1) >> 1) & 3);
    __half* hb = hstate + (size_t)p * 32 + sch * 8 + (fq & 7);
    *reinterpret_cast<__half2*>(hb)     = __floats2half2_rn(hv.x, hv.y);
    *reinterpret_cast<__half2*>(hb + 2) = __floats2half2_rn(hv.z, hv.w);
    size_t oo = (frame * HWPX + pix) * 32 + fq;
    if (MODE == 1) {
        *reinterpret_cast<float4*>(out0 + oo) = hv;
        float s[4], bb[4], o16[4];
        #pragma unroll
        for (int i = 0; i < 4; ++i) {
            s[i] = __ldg(g1 + fq + i) * rsqrtf(__ldg(va1 + fq + i) + 1e-3f);
            bb[i] = __ldg(be1 + fq + i) - __ldg(mu1 + fq + i) * s[i];
        }
        o16[0] = fmaf(hv.x, s[0], bb[0]); o16[1] = fmaf(hv.y, s[1], bb[1]);
        o16[2] = fmaf(hv.z, s[2], bb[2]); o16[3] = fmaf(hv.w, s[3], bb[3]);
        __half* ob = out16 + (frame * HWPX + pix) * 32 + sch * 8 + (fq & 7);
        *reinterpret_cast<__half2*>(ob)     = __floats2half2_rn(o16[0], o16[1]);
        *reinterpret_cast<__half2*>(ob + 2) = __floats2half2_rn(o16[2], o16[3]);
    } else {
        float4 rv = *reinterpret_cast<const float4*>(res + oo);
        hv.x += rv.x; hv.y += rv.y; hv.z += rv.z; hv.w += rv.w;
        *reinterpret_cast<float4*>(outF + oo) = hv;
    }
}

// ---------------------------------------------------------------------------
extern "C" void kernel_launch(void* const* d_in, const int* in_sizes, int n_in,
                              void* d_out, int out_size)
{
    (void)in_sizes; (void)n_in; (void)out_size;
    const float* x    = (const float*)d_in[0];
    const float* gma  = (const float*)d_in[1];
    const float* bta  = (const float*)d_in[2];
    const float* mu   = (const float*)d_in[3];
    const float* var  = (const float*)d_in[4];
    const float* ker  = (const float*)d_in[5];
    const float* rker = (const float*)d_in[6];
    const float* bias = (const float*)d_in[7];

    __half *xf16, *x2f16, *w16, *rw16, *h16;
    float *xz, *cst, *l0;
    cudaGetSymbolAddress((void**)&xf16,  g_xf16);
    cudaGetSymbolAddress((void**)&x2f16, g_x2f16);
    cudaGetSymbolAddress((void**)&w16,   g_w16);
    cudaGetSymbolAddress((void**)&rw16,  g_rw16);
    cudaGetSymbolAddress((void**)&xz,    g_xz);
    cudaGetSymbolAddress((void**)&cst,   g_c);
    cudaGetSymbolAddress((void**)&h16,   g_h16);
    cudaGetSymbolAddress((void**)&l0,    g_l0);

    const size_t SMEM = (8448 + 36864) * sizeof(__half);   // 90624 B
    cudaFuncSetAttribute((const void*)conv_mma<0>, cudaFuncAttributeMaxDynamicSharedMemorySize, (int)SMEM);
    cudaFuncSetAttribute((const void*)conv_mma<1>, cudaFuncAttributeMaxDynamicSharedMemorySize, (int)SMEM);
    cudaFuncSetAttribute((const void*)conv_mma<2>, cudaFuncAttributeMaxDynamicSharedMemorySize, (int)SMEM);

    prep_w<<<576, 256>>>(ker, rker);
    prep_x<<<4096, 256>>>(x, gma, bta, mu, var);

    float* outF = (float*)d_out;

    // ---- layer 0 ----
    conv_mma<0><<<dim3(32, NFRM), 256, SMEM>>>(
        xf16, w16, bias, nullptr, nullptr, nullptr, nullptr, nullptr,
        nullptr, xz, nullptr, nullptr, nullptr, nullptr, 0);
    gate0<1><<<512, 256>>>(xz, cst, h16, l0, x2f16, nullptr, nullptr,
                           gma + 32, bta + 32, mu + 32, var + 32);
    for (int t = 1; t < NT; ++t)
        conv_mma<1><<<dim3(32, NB), 256, SMEM>>>(
            h16, rw16, nullptr, xz, cst, h16, l0, x2f16, nullptr, nullptr,
            gma + 32, bta + 32, mu + 32, var + 32, t);

    // ---- layer 1 ----
    conv_mma<0><<<dim3(32, NFRM), 256, SMEM>>>(
        x2f16, w16 + 36864, bias + 128, nullptr, nullptr, nullptr, nullptr, nullptr,
        nullptr, xz, nullptr, nullptr, nullptr, nullptr, 0);
    gate0<2><<<512, 256>>>(xz, cst, h16, nullptr, nullptr, l0, outF,
                           nullptr, nullptr, nullptr, nullptr);
    for (int t = 1; t < NT; ++t)
        conv_mma<2><<<dim3(32, NB), 256, SMEM>>>(
            h16, rw16 + 36864, nullptr, xz, cst, h16, nullptr, nullptr, l0, outF,
            nullptr, nullptr, nullptr, nullptr, t);
}